// round 12
// baseline (speedup 1.0000x reference)
#include <cuda_runtime.h>

#define T_SAMPLES 8388608
#define NFFT 512
#define HOP 128
#define PAD 256
#define NFRAMES 65537          // 1 + (T + 2*PAD - NFFT)/HOP
#define NPAIR 129              // mirror pairs (k, 256-k), k = 0..128
#define FPB 64                 // frames per block
#define NBLKS 1025             // ceil(NFRAMES / FPB)
#define NWARP 16
#define SUBF 4                 // frames per warp subchunk
#define BLK_SPAN (FPB * HOP)   // 8192
#define ACC_SPAN (SUBF * HOP + (NFFT - HOP))  // 896 floats
#define OVER (NFFT - HOP)      // 384
#define NSUP 41                // superchunks: 1025 = 41 * 25
#define SUPLEN 25
#define DECAYF 0.999f
#define PI_D 3.14159265358979323846

// XOR swizzle: kills bank conflicts on bit-reversed float2 scatters/gathers.
#define SWZ(p) ((p) ^ (((p) >> 4) & 0x0F))

// ---------------- global scratch ----------------
__device__ float4 g_pair[(size_t)NFRAMES * NPAIR];      // (E, P) per mirror pair, ~135MB
__device__ float2 g_subprefP[NBLKS * NWARP * NPAIR];    // within-block exclusive prefixes
__device__ float2 g_blkP[NBLKS * NPAIR];                // per-block inclusive summaries
__device__ float2 g_blkprefP[NBLKS * NPAIR];            // cross-block exclusive prefixes
__device__ float2 g_supP[NSUP * NPAIR];                 // superchunk inclusive totals
__device__ float2 g_supprefP[NSUP * NPAIR];             // superchunk exclusive prefixes
__device__ float  g_head[NBLKS * OVER];
__device__ float  g_tail[NBLKS * OVER];
__device__ float2 g_W512[512];
__device__ float  g_win[512];
__device__ float  g_D4, g_D64, g_D1600;
__device__ float  g_Dpow4[NWARP];                       // DECAY^(4*w)

__device__ __forceinline__ float2 cmul(float2 a, float2 b) {
    return make_float2(a.x * b.x - a.y * b.y, a.x * b.y + a.y * b.x);
}
__device__ __forceinline__ float2 csub(float2 a, float2 b) {
    return make_float2(a.x - b.x, a.y - b.y);
}
__device__ __forceinline__ float2 cadd(float2 a, float2 b) {
    return make_float2(a.x + b.x, a.y + b.y);
}
__device__ __forceinline__ int brev8(int x) { return (int)(__brev((unsigned)x) >> 24); }
__device__ __forceinline__ int rev5(int x) { return (int)(__brev((unsigned)x) >> 27); }

// ---------------- tables ----------------
__global__ void init_tables() {
    int i = threadIdx.x;  // 512 threads
    double ang = -2.0 * PI_D * (double)i / 512.0;
    g_W512[i] = make_float2((float)cos(ang), (float)sin(ang));
    g_win[i]  = (float)(0.5 * (1.0 - cos(2.0 * PI_D * (double)i / 512.0)));
    if (i < NWARP) g_Dpow4[i] = (float)pow((double)DECAYF, 4.0 * i);
    if (i == 0) {
        g_D4    = (float)pow((double)DECAYF, 4.0);
        g_D64   = (float)pow((double)DECAYF, 64.0);
        g_D1600 = (float)pow((double)DECAYF, 1600.0);
    }
}

// ---------------- warp-level 256-pt complex FFT (DIF radix-2, slim butterflies) ----------------
__device__ __forceinline__ void warp_fft256(float2 r[8], int lane, const float2* s_W) {
#pragma unroll
    for (int j = 0; j < 4; j++) {
        float2 a = r[j], b = r[j + 4];
        float2 w = s_W[2 * (32 * j + lane)];
        r[j] = cadd(a, b);
        r[j + 4] = cmul(csub(a, b), w);
    }
#pragma unroll
    for (int half = 0; half < 2; half++) {
#pragma unroll
        for (int j = 0; j < 2; j++) {
            int lo = half * 4 + j;
            float2 a = r[lo], b = r[lo + 2];
            float2 w = s_W[4 * (32 * j + lane)];
            r[lo] = cadd(a, b);
            r[lo + 2] = cmul(csub(a, b), w);
        }
    }
    {
        float2 w = s_W[8 * lane];
#pragma unroll
        for (int q = 0; q < 4; q++) {
            int lo = 2 * q;
            float2 a = r[lo], b = r[lo + 1];
            r[lo] = cadd(a, b);
            r[lo + 1] = cmul(csub(a, b), w);
        }
    }
#pragma unroll
    for (int sidx = 0; sidx < 4; sidx++) {
        const int m = 16 >> sidx;
        bool up = (lane & m) != 0;
        float sgn = up ? -1.0f : 1.0f;
        float2 tw = s_W[(256 / m) * (lane & (m - 1))];
        float2 w_eff = up ? tw : make_float2(1.0f, 0.0f);
#pragma unroll
        for (int j = 0; j < 8; j++) {
            float ox = __shfl_xor_sync(0xffffffffu, r[j].x, m);
            float oy = __shfl_xor_sync(0xffffffffu, r[j].y, m);
            float sx = fmaf(sgn, r[j].x, ox);
            float sy = fmaf(sgn, r[j].y, oy);
            r[j] = cmul(make_float2(sx, sy), w_eff);
        }
    }
    {
        float sgn = (lane & 1) ? -1.0f : 1.0f;
#pragma unroll
        for (int j = 0; j < 8; j++) {
            float ox = __shfl_xor_sync(0xffffffffu, r[j].x, 1);
            float oy = __shfl_xor_sync(0xffffffffu, r[j].y, 1);
            r[j] = make_float2(fmaf(sgn, r[j].x, ox), fmaf(sgn, r[j].y, oy));
        }
    }
}

// ---------------- frame load with hoisted window regs ----------------
__device__ __forceinline__ void load_frame(const float* __restrict__ x, int f, int lane,
                                           const float2 win2p[8], float2 r[8]) {
    int p0 = f * HOP - PAD;
    if (p0 >= 0 && p0 + NFFT <= T_SAMPLES) {
        const float2* xv = (const float2*)(x + p0);
#pragma unroll
        for (int j = 0; j < 8; j++) {
            int k = 32 * j + lane;
            float2 v = xv[k];
            r[j] = make_float2(v.x * win2p[j].x, v.y * win2p[j].y);
        }
    } else {
#pragma unroll
        for (int j = 0; j < 8; j++) {
            int k = 32 * j + lane;
            int pa = p0 + 2 * k, pb = pa + 1;
            if (pa < 0) pa = -pa; else if (pa >= T_SAMPLES) pa = 2 * T_SAMPLES - 2 - pa;
            if (pb < 0) pb = -pb; else if (pb >= T_SAMPLES) pb = 2 * T_SAMPLES - 2 - pb;
            r[j] = make_float2(x[pa] * win2p[j].x, x[pb] * win2p[j].y);
        }
    }
}

// swizzled float read from a warp acc region (off = float index 0..ACC_SPAN-1)
__device__ __forceinline__ float accRead(const float2* accW, int off) {
    int q = off >> 1;
    const float* p = (const float*)(accW + SWZ(q));
    return p[off & 1];
}

// bit-reverse of j within 3 bits (compile-time per unrolled j)
__device__ __forceinline__ constexpr int rev3c(int j) {
    return ((j & 1) << 2) | (j & 2) | ((j >> 2) & 1);
}

// ---------------- smem layouts ----------------
struct SmemA {
    float2 W[512];
    float2 win2[256];
    float2 Z[NWARP][256];
    float2 subP[NWARP][NPAIR];
};
struct SmemB {
    float2 W[512];
    float2 win2[256];
    float2 Z[NWARP][256];
    float2 acc[NWARP][ACC_SPAN / 2];   // 448 float2 per warp, swizzled layout
};

// ---------------- phase A: FFT -> paired (E,P) spectrum + runmax summaries ----------------
__global__ __launch_bounds__(512, 2) void phaseA(const float* __restrict__ x) {
    extern __shared__ char raw[];
    SmemA* sm = (SmemA*)raw;
    int t = threadIdx.x, lane = t & 31, w = t >> 5, b = blockIdx.x;
    sm->W[t] = g_W512[t];
    if (t < 256) sm->win2[t] = make_float2(g_win[2 * t], g_win[2 * t + 1]);
    __syncthreads();

    float2* Zs = sm->Z[w];
    float2 win2p[8];
#pragma unroll
    for (int j = 0; j < 8; j++) win2p[j] = sm->win2[32 * j + lane];

    float rA[5], rB[5];
#pragma unroll
    for (int u = 0; u < 5; u++) { rA[u] = 0.0f; rB[u] = 0.0f; }

    int f0 = b * FPB + w * SUBF;
    for (int i = 0; i < SUBF; i++) {
        int f = f0 + i;
        if (f >= NFRAMES) break;
        float2 r[8];
        load_frame(x, f, lane, win2p, r);
        warp_fft256(r, lane, sm->W);
#pragma unroll
        for (int j = 0; j < 8; j++) Zs[SWZ(brev8(32 * j + lane))] = r[j];
        __syncwarp();

        size_t base = (size_t)f * NPAIR;
#pragma unroll
        for (int u = 0; u < 5; u++) {
            int k = (u < 4) ? 32 * u + lane : 128;
            bool active = (u < 4) || (lane == 0);
            if (active) {
                float2 zk = Zs[SWZ(k)];
                float2 zm = Zs[SWZ((256 - k) & 255)];
                float2 E = make_float2(0.5f * (zk.x + zm.x), 0.5f * (zk.y - zm.y));
                float2 d = make_float2(0.5f * (zk.x - zm.x), 0.5f * (zk.y + zm.y));
                float2 mid = make_float2(d.y, -d.x);          // -i * d
                float2 P = cmul(sm->W[k], mid);
                g_pair[base + k] = make_float4(E.x, E.y, P.x, P.y);
                float ax = E.x + P.x, ay = E.y + P.y;
                float bx = E.x - P.x, by = E.y - P.y;
                rA[u] = fmaxf(DECAYF * rA[u], sqrtf(ax * ax + ay * ay));
                rB[u] = fmaxf(DECAYF * rB[u], sqrtf(bx * bx + by * by));
            }
        }
        __syncwarp();
    }
#pragma unroll
    for (int u = 0; u < 5; u++) {
        int k = (u < 4) ? 32 * u + lane : 128;
        bool active = (u < 4) || (lane == 0);
        if (active) sm->subP[w][k] = make_float2(rA[u], rB[u]);
    }
    __syncthreads();
    // block summary + within-block exclusive prefixes (float view width 2*NPAIR = 258)
    if (t < 2 * NPAIR) {
        float D4 = g_D4;
        const float* subF = (const float*)sm->subP;
        float carry = 0.0f;
#pragma unroll
        for (int j = 0; j < NWARP; j++) {
            ((float*)g_subprefP)[(b * NWARP + j) * 2 * NPAIR + t] = carry;
            carry = fmaxf(D4 * carry, subF[j * 2 * NPAIR + t]);
        }
        ((float*)g_blkP)[b * 2 * NPAIR + t] = carry;
    }
}

// ---------------- 3-level cross-block scan (no grid barrier, no atomics) ----------------
__global__ __launch_bounds__(288) void midscanA() {
    int t = threadIdx.x;
    if (t >= 2 * NPAIR) return;
    int s = blockIdx.x;
    const float* blkF = (const float*)g_blkP;
    float D64 = g_D64;
    float v[SUPLEN];
#pragma unroll
    for (int j = 0; j < SUPLEN; j++) v[j] = blkF[(s * SUPLEN + j) * 2 * NPAIR + t];
    float carry = 0.0f;
#pragma unroll
    for (int j = 0; j < SUPLEN; j++) carry = fmaxf(D64 * carry, v[j]);
    ((float*)g_supP)[s * 2 * NPAIR + t] = carry;
}

__global__ __launch_bounds__(288) void midscanB() {
    int t = threadIdx.x;
    if (t >= 2 * NPAIR) return;
    const float* supF = (const float*)g_supP;
    float D1600 = g_D1600;
    float v[NSUP];
#pragma unroll
    for (int s = 0; s < NSUP; s++) v[s] = supF[s * 2 * NPAIR + t];
    float carry = 0.0f;
#pragma unroll
    for (int s = 0; s < NSUP; s++) {
        ((float*)g_supprefP)[s * 2 * NPAIR + t] = carry;
        carry = fmaxf(D1600 * carry, v[s]);
    }
}

__global__ __launch_bounds__(288) void midscanC() {
    int t = threadIdx.x;
    if (t >= 2 * NPAIR) return;
    int s = blockIdx.x;
    const float* blkF = (const float*)g_blkP;
    float D64 = g_D64;
    float v[SUPLEN];
#pragma unroll
    for (int j = 0; j < SUPLEN; j++) v[j] = blkF[(s * SUPLEN + j) * 2 * NPAIR + t];
    float carry = ((const float*)g_supprefP)[s * 2 * NPAIR + t];
#pragma unroll
    for (int j = 0; j < SUPLEN; j++) {
        ((float*)g_blkprefP)[(s * SUPLEN + j) * 2 * NPAIR + t] = carry;
        carry = fmaxf(D64 * carry, v[j]);
    }
}

// ---------------- phase B: gain+repack, inverse FFT, direct scattered OLA ----------------
__global__ __launch_bounds__(512, 2) void phaseB(float* __restrict__ out) {
    extern __shared__ char raw[];
    SmemB* sm = (SmemB*)raw;
    int t = threadIdx.x, lane = t & 31, w = t >> 5, b = blockIdx.x;
    sm->W[t] = g_W512[t];
    if (t < 256) sm->win2[t] = make_float2(g_win[2 * t], g_win[2 * t + 1]);
    for (int i = t; i < NWARP * (ACC_SPAN / 2); i += 512)
        ((float2*)sm->acc)[i] = make_float2(0.0f, 0.0f);
    __syncthreads();

    float2* Zs = sm->Z[w];
    float2* accW = sm->acc[w];
    const int revl = 8 * rev5(lane);       // bit-reversed lane base (hoisted)

    // hoisted window values at bit-reversed float2 positions
    float2 winp[8];
#pragma unroll
    for (int j = 0; j < 8; j++) winp[j] = sm->win2[revl + rev3c(j)];

    float dw = g_Dpow4[w];
    float rA[5], rB[5];
    // running max init: r = max(D^(4w) * blockprefix, within-block prefix)
#pragma unroll
    for (int u = 0; u < 5; u++) {
        int k = (u < 4) ? 32 * u + lane : 128;
        bool active = (u < 4) || (lane == 0);
        float2 p = make_float2(0.0f, 0.0f);
        if (active) {
            float2 bp = g_blkprefP[b * NPAIR + k];
            float2 sp = g_subprefP[(b * NWARP + w) * NPAIR + k];
            p.x = fmaxf(dw * bp.x, sp.x);
            p.y = fmaxf(dw * bp.y, sp.y);
        }
        rA[u] = p.x; rB[u] = p.y;
    }

    int f0 = b * FPB + w * SUBF;
    const float scale = 1.0f / 256.0f;
    for (int i = 0; i < SUBF; i++) {
        int f = f0 + i;
        if (f >= NFRAMES) break;
        size_t base = (size_t)f * NPAIR;

#pragma unroll
        for (int u = 0; u < 5; u++) {
            int k = (u < 4) ? 32 * u + lane : 128;
            bool active = (u < 4) || (lane == 0);
            if (active) {
                float4 c = g_pair[base + k];
                float2 E = make_float2(c.x, c.y);
                float2 P = make_float2(c.z, c.w);
                float ax = E.x + P.x, ay = E.y + P.y;
                float bx = E.x - P.x, by = E.y - P.y;
                float ma2 = ax * ax + ay * ay;
                float mb2 = bx * bx + by * by;
                float ra = fmaxf(DECAYF * rA[u], sqrtf(ma2)); rA[u] = ra;
                float rb = fmaxf(DECAYF * rB[u], sqrtf(mb2)); rB[u] = rb;
                float ga = ma2 / (fmaxf(0.5f * ra * ra, 1e-8f) + ma2);
                float gb = mb2 / (fmaxf(0.5f * rb * rb, 1e-8f) + mb2);
                float s = 0.5f * (ga + gb), md = 0.5f * (ga - gb);
                float2 ze = make_float2(s * E.x + md * P.x, s * E.y + md * P.y);
                float2 d2 = make_float2(md * E.x + s * P.x, md * E.y + s * P.y);
                float2 tw = sm->W[k];
                float2 zo = make_float2(tw.x * d2.x + tw.y * d2.y,
                                        tw.x * d2.y - tw.y * d2.x);
                Zs[SWZ(k)] = make_float2(ze.x - zo.y, -(ze.y + zo.x));
                if (k >= 1 && k <= 127)
                    Zs[SWZ(256 - k)] = make_float2(ze.x + zo.y, ze.y - zo.x);
            }
        }
        __syncwarp();

        float2 r[8];
#pragma unroll
        for (int j = 0; j < 8; j++) r[j] = Zs[SWZ(32 * j + lane)];
        warp_fft256(r, lane, sm->W);

        // direct scattered accumulate into warp-private acc (swizzled, conflict-free)
        int qbase = i * 64 + revl;
#pragma unroll
        for (int j = 0; j < 8; j++) {
            int q = qbase + rev3c(j);
            int sq = SWZ(q);
            float2 cur = accW[sq];
            cur.x = fmaf(r[j].x * scale, winp[j].x, cur.x);
            cur.y = fmaf(-r[j].y * scale, winp[j].y, cur.y);
            accW[sq] = cur;
        }
        __syncwarp();
    }
    __syncthreads();

    // combine warp regions & write normalized interior output.
    // Interior: exactly 4 overlapping Hann frames -> sum win^2 = 1.5.
    const float INV_NORM = 1.0f / 1.5f;
    int t0 = b * BLK_SPAN;
    for (int s = t; s < BLK_SPAN; s += 512) {
        int wo = s >> 9;          // 512 samples per warp region
        int off = s & 511;
        float val = accRead(sm->acc[wo], off);
        if (off < OVER && wo > 0) val += accRead(sm->acc[wo - 1], 512 + off);
        if (s < OVER) {
            g_head[b * OVER + s] = val;
        } else {
            int tt = t0 + s;
            if (tt >= PAD && tt < PAD + T_SAMPLES) out[tt - PAD] = val * INV_NORM;
        }
    }
    if (t < OVER) g_tail[b * OVER + t] = accRead(sm->acc[NWARP - 1], 512 + t);
}

// ---------------- fixup: block-boundary samples (general win^2 loop) ----------------
__global__ __launch_bounds__(384) void fixup(float* __restrict__ out) {
    int b = blockIdx.x;
    int i = threadIdx.x;
    int tt = b * BLK_SPAN + i;
    float val = g_head[b * OVER + i] + (b > 0 ? g_tail[(b - 1) * OVER + i] : 0.0f);
    if (tt >= PAD && tt < PAD + T_SAMPLES) {
        int fmax_ = tt >> 7; if (fmax_ > NFRAMES - 1) fmax_ = NFRAMES - 1;
        int fmin_ = (tt - OVER) >> 7; if (fmin_ < 0) fmin_ = 0;
        float ws = 0.0f;
        for (int fr = fmin_; fr <= fmax_; fr++) {
            float wv = g_win[tt - (fr << 7)];
            ws += wv * wv;
        }
        out[tt - PAD] = val / fmaxf(ws, 1e-11f);
    }
}

// ---------------- launch ----------------
extern "C" void kernel_launch(void* const* d_in, const int* in_sizes, int n_in,
                              void* d_out, int out_size) {
    const float* x = (const float*)d_in[0];
    float* out = (float*)d_out;

    static bool attr_done = false;
    if (!attr_done) {
        cudaFuncSetAttribute(phaseA, cudaFuncAttributeMaxDynamicSharedMemorySize,
                             (int)sizeof(SmemA));
        cudaFuncSetAttribute(phaseB, cudaFuncAttributeMaxDynamicSharedMemorySize,
                             (int)sizeof(SmemB));
        attr_done = true;
    }

    init_tables<<<1, 512>>>();
    phaseA<<<NBLKS, 512, sizeof(SmemA)>>>(x);
    midscanA<<<NSUP, 288>>>();
    midscanB<<<1, 288>>>();
    midscanC<<<NSUP, 288>>>();
    phaseB<<<NBLKS, 512, sizeof(SmemB)>>>(out);
    fixup<<<NBLKS, 384>>>(out);
}

// round 13
// speedup vs baseline: 1.0086x; 1.0086x over previous
#include <cuda_runtime.h>

#define T_SAMPLES 8388608
#define NFFT 512
#define HOP 128
#define PAD 256
#define NFRAMES 65537          // 1 + (T + 2*PAD - NFFT)/HOP
#define NPAIR 129              // mirror pairs (k, 256-k), k = 0..128
#define FPB 32                 // frames per block
#define NBLKS 2049             // ceil(NFRAMES / FPB)
#define NWARP 16
#define SUBF 2                 // frames per warp subchunk
#define BLK_SPAN (FPB * HOP)   // 4096
#define ACC_SPAN (SUBF * HOP + (NFFT - HOP))  // 640 floats
#define OVER (NFFT - HOP)      // 384
#define NSUP 65                // superchunks: 65 * 32 = 2080 >= 2049
#define SUPLEN 32
#define DECAYF 0.999f
#define PI_D 3.14159265358979323846

// XOR swizzle: kills bank conflicts on bit-reversed float2 scatters/gathers.
#define SWZ(p) ((p) ^ (((p) >> 4) & 0x0F))

// ---------------- global scratch ----------------
__device__ float4 g_pair[(size_t)NFRAMES * NPAIR];          // (E, P) per mirror pair, ~135MB
__device__ float2 g_subprefP[(size_t)NBLKS * NWARP * NPAIR];// within-block exclusive prefixes
__device__ float2 g_blkP[NSUP * SUPLEN * NPAIR];            // per-block inclusive summaries
__device__ float2 g_blkprefP[NSUP * SUPLEN * NPAIR];        // cross-block exclusive prefixes
__device__ float2 g_supP[NSUP * NPAIR];                     // superchunk inclusive totals
__device__ float2 g_supprefP[NSUP * NPAIR];                 // superchunk exclusive prefixes
__device__ float  g_head[(size_t)NBLKS * OVER];
__device__ float  g_tail[(size_t)NBLKS * OVER];
__device__ float2 g_W512[512];
__device__ float  g_win[512];
__device__ float  g_D2, g_D32, g_D1024;
__device__ float  g_DpowS[NWARP];                           // DECAY^(SUBF*w)

__device__ __forceinline__ float2 cmul(float2 a, float2 b) {
    return make_float2(a.x * b.x - a.y * b.y, a.x * b.y + a.y * b.x);
}
__device__ __forceinline__ float2 csub(float2 a, float2 b) {
    return make_float2(a.x - b.x, a.y - b.y);
}
__device__ __forceinline__ float2 cadd(float2 a, float2 b) {
    return make_float2(a.x + b.x, a.y + b.y);
}
__device__ __forceinline__ int brev8(int x) { return (int)(__brev((unsigned)x) >> 24); }

// ---------------- tables ----------------
__global__ void init_tables() {
    int i = threadIdx.x;  // 512 threads
    double ang = -2.0 * PI_D * (double)i / 512.0;
    g_W512[i] = make_float2((float)cos(ang), (float)sin(ang));
    g_win[i]  = (float)(0.5 * (1.0 - cos(2.0 * PI_D * (double)i / 512.0)));
    if (i < NWARP) g_DpowS[i] = (float)pow((double)DECAYF, (double)(SUBF * i));
    if (i == 0) {
        g_D2    = (float)pow((double)DECAYF, (double)SUBF);
        g_D32   = (float)pow((double)DECAYF, (double)FPB);
        g_D1024 = (float)pow((double)DECAYF, (double)(FPB * SUPLEN));
    }
}

// ---------------- warp-level 256-pt complex FFT (DIF radix-2, slim butterflies) ----------------
__device__ __forceinline__ void warp_fft256(float2 r[8], int lane, const float2* s_W) {
#pragma unroll
    for (int j = 0; j < 4; j++) {
        float2 a = r[j], b = r[j + 4];
        float2 w = s_W[2 * (32 * j + lane)];
        r[j] = cadd(a, b);
        r[j + 4] = cmul(csub(a, b), w);
    }
#pragma unroll
    for (int half = 0; half < 2; half++) {
#pragma unroll
        for (int j = 0; j < 2; j++) {
            int lo = half * 4 + j;
            float2 a = r[lo], b = r[lo + 2];
            float2 w = s_W[4 * (32 * j + lane)];
            r[lo] = cadd(a, b);
            r[lo + 2] = cmul(csub(a, b), w);
        }
    }
    {
        float2 w = s_W[8 * lane];
#pragma unroll
        for (int q = 0; q < 4; q++) {
            int lo = 2 * q;
            float2 a = r[lo], b = r[lo + 1];
            r[lo] = cadd(a, b);
            r[lo + 1] = cmul(csub(a, b), w);
        }
    }
#pragma unroll
    for (int sidx = 0; sidx < 4; sidx++) {
        const int m = 16 >> sidx;
        bool up = (lane & m) != 0;
        float sgn = up ? -1.0f : 1.0f;
        float2 tw = s_W[(256 / m) * (lane & (m - 1))];
        float2 w_eff = up ? tw : make_float2(1.0f, 0.0f);
#pragma unroll
        for (int j = 0; j < 8; j++) {
            float ox = __shfl_xor_sync(0xffffffffu, r[j].x, m);
            float oy = __shfl_xor_sync(0xffffffffu, r[j].y, m);
            float sx = fmaf(sgn, r[j].x, ox);
            float sy = fmaf(sgn, r[j].y, oy);
            r[j] = cmul(make_float2(sx, sy), w_eff);
        }
    }
    {
        float sgn = (lane & 1) ? -1.0f : 1.0f;
#pragma unroll
        for (int j = 0; j < 8; j++) {
            float ox = __shfl_xor_sync(0xffffffffu, r[j].x, 1);
            float oy = __shfl_xor_sync(0xffffffffu, r[j].y, 1);
            r[j] = make_float2(fmaf(sgn, r[j].x, ox), fmaf(sgn, r[j].y, oy));
        }
    }
}

// ---------------- frame load with hoisted window regs ----------------
__device__ __forceinline__ void load_frame(const float* __restrict__ x, int f, int lane,
                                           const float2 win2p[8], float2 r[8]) {
    int p0 = f * HOP - PAD;
    if (p0 >= 0 && p0 + NFFT <= T_SAMPLES) {
        const float2* xv = (const float2*)(x + p0);
#pragma unroll
        for (int j = 0; j < 8; j++) {
            int k = 32 * j + lane;
            float2 v = xv[k];
            r[j] = make_float2(v.x * win2p[j].x, v.y * win2p[j].y);
        }
    } else {
#pragma unroll
        for (int j = 0; j < 8; j++) {
            int k = 32 * j + lane;
            int pa = p0 + 2 * k, pb = pa + 1;
            if (pa < 0) pa = -pa; else if (pa >= T_SAMPLES) pa = 2 * T_SAMPLES - 2 - pa;
            if (pb < 0) pb = -pb; else if (pb >= T_SAMPLES) pb = 2 * T_SAMPLES - 2 - pb;
            r[j] = make_float2(x[pa] * win2p[j].x, x[pb] * win2p[j].y);
        }
    }
}

// ---------------- smem layouts ----------------
struct SmemA {
    float2 W[512];
    float2 win2[256];
    float2 Z[NWARP][256];
    float2 subP[NWARP][NPAIR];
};
struct SmemB {
    float2 W[512];
    float2 win2[256];
    float2 Z[NWARP][256];
    float2 acc[NWARP][ACC_SPAN / 2];   // 320 float2 per warp, linear layout
};

// ---------------- phase A: FFT -> paired (E,P) spectrum + runmax summaries ----------------
__global__ __launch_bounds__(512, 2) void phaseA(const float* __restrict__ x) {
    extern __shared__ char raw[];
    SmemA* sm = (SmemA*)raw;
    int t = threadIdx.x, lane = t & 31, w = t >> 5, b = blockIdx.x;
    sm->W[t] = g_W512[t];
    if (t < 256) sm->win2[t] = make_float2(g_win[2 * t], g_win[2 * t + 1]);
    __syncthreads();

    float2* Zs = sm->Z[w];
    float2 win2p[8];
#pragma unroll
    for (int j = 0; j < 8; j++) win2p[j] = sm->win2[32 * j + lane];

    float rA[5], rB[5];
#pragma unroll
    for (int u = 0; u < 5; u++) { rA[u] = 0.0f; rB[u] = 0.0f; }

    int f0 = b * FPB + w * SUBF;
#pragma unroll
    for (int i = 0; i < SUBF; i++) {
        int f = f0 + i;
        if (f >= NFRAMES) break;
        float2 r[8];
        load_frame(x, f, lane, win2p, r);
        warp_fft256(r, lane, sm->W);
#pragma unroll
        for (int j = 0; j < 8; j++) Zs[SWZ(brev8(32 * j + lane))] = r[j];
        __syncwarp();

        size_t base = (size_t)f * NPAIR;
#pragma unroll
        for (int u = 0; u < 5; u++) {
            int k = (u < 4) ? 32 * u + lane : 128;
            bool active = (u < 4) || (lane == 0);
            if (active) {
                float2 zk = Zs[SWZ(k)];
                float2 zm = Zs[SWZ((256 - k) & 255)];
                float2 E = make_float2(0.5f * (zk.x + zm.x), 0.5f * (zk.y - zm.y));
                float2 d = make_float2(0.5f * (zk.x - zm.x), 0.5f * (zk.y + zm.y));
                float2 mid = make_float2(d.y, -d.x);          // -i * d
                float2 P = cmul(sm->W[k], mid);
                g_pair[base + k] = make_float4(E.x, E.y, P.x, P.y);
                float ax = E.x + P.x, ay = E.y + P.y;
                float bx = E.x - P.x, by = E.y - P.y;
                rA[u] = fmaxf(DECAYF * rA[u], sqrtf(ax * ax + ay * ay));
                rB[u] = fmaxf(DECAYF * rB[u], sqrtf(bx * bx + by * by));
            }
        }
        __syncwarp();
    }
#pragma unroll
    for (int u = 0; u < 5; u++) {
        int k = (u < 4) ? 32 * u + lane : 128;
        bool active = (u < 4) || (lane == 0);
        if (active) sm->subP[w][k] = make_float2(rA[u], rB[u]);
    }
    __syncthreads();
    // block summary + within-block exclusive prefixes (float view width 2*NPAIR = 258)
    if (t < 2 * NPAIR) {
        float D2 = g_D2;
        const float* subF = (const float*)sm->subP;
        float carry = 0.0f;
#pragma unroll
        for (int j = 0; j < NWARP; j++) {
            ((float*)g_subprefP)[((size_t)b * NWARP + j) * 2 * NPAIR + t] = carry;
            carry = fmaxf(D2 * carry, subF[j * 2 * NPAIR + t]);
        }
        ((float*)g_blkP)[(size_t)b * 2 * NPAIR + t] = carry;
    }
}

// ---------------- 3-level cross-block scan (no grid barrier, no atomics) ----------------
__global__ __launch_bounds__(288) void midscanA() {
    int t = threadIdx.x;
    if (t >= 2 * NPAIR) return;
    int s = blockIdx.x;
    const float* blkF = (const float*)g_blkP;
    float D32 = g_D32;
    float v[SUPLEN];
#pragma unroll
    for (int j = 0; j < SUPLEN; j++) {
        int bb = s * SUPLEN + j;
        v[j] = (bb < NBLKS) ? blkF[(size_t)bb * 2 * NPAIR + t] : 0.0f;
    }
    float carry = 0.0f;
#pragma unroll
    for (int j = 0; j < SUPLEN; j++) carry = fmaxf(D32 * carry, v[j]);
    ((float*)g_supP)[s * 2 * NPAIR + t] = carry;
}

__global__ __launch_bounds__(288) void midscanB() {
    int t = threadIdx.x;
    if (t >= 2 * NPAIR) return;
    const float* supF = (const float*)g_supP;
    float D1024 = g_D1024;
    float v[NSUP];
#pragma unroll
    for (int s = 0; s < NSUP; s++) v[s] = supF[s * 2 * NPAIR + t];
    float carry = 0.0f;
#pragma unroll
    for (int s = 0; s < NSUP; s++) {
        ((float*)g_supprefP)[s * 2 * NPAIR + t] = carry;
        carry = fmaxf(D1024 * carry, v[s]);
    }
}

__global__ __launch_bounds__(288) void midscanC() {
    int t = threadIdx.x;
    if (t >= 2 * NPAIR) return;
    int s = blockIdx.x;
    const float* blkF = (const float*)g_blkP;
    float D32 = g_D32;
    float v[SUPLEN];
#pragma unroll
    for (int j = 0; j < SUPLEN; j++) {
        int bb = s * SUPLEN + j;
        v[j] = (bb < NBLKS) ? blkF[(size_t)bb * 2 * NPAIR + t] : 0.0f;
    }
    float carry = ((const float*)g_supprefP)[s * 2 * NPAIR + t];
#pragma unroll
    for (int j = 0; j < SUPLEN; j++) {
        int bb = s * SUPLEN + j;
        if (bb < NBLKS)
            ((float*)g_blkprefP)[(size_t)bb * 2 * NPAIR + t] = carry;
        carry = fmaxf(D32 * carry, v[j]);
    }
}

// ---------------- phase B: gain+repack, inverse FFT, staged linear OLA ----------------
__global__ __launch_bounds__(512, 2) void phaseB(float* __restrict__ out) {
    extern __shared__ char raw[];
    SmemB* sm = (SmemB*)raw;
    int t = threadIdx.x, lane = t & 31, w = t >> 5, b = blockIdx.x;
    sm->W[t] = g_W512[t];
    if (t < 256) sm->win2[t] = make_float2(g_win[2 * t], g_win[2 * t + 1]);
    for (int i = t; i < NWARP * (ACC_SPAN / 2); i += 512)
        ((float2*)sm->acc)[i] = make_float2(0.0f, 0.0f);
    __syncthreads();

    float2* Zs = sm->Z[w];
    float dw = g_DpowS[w];
    float rA[5], rB[5];
    // running max init: r = max(D^(SUBF*w) * blockprefix, within-block prefix)
#pragma unroll
    for (int u = 0; u < 5; u++) {
        int k = (u < 4) ? 32 * u + lane : 128;
        bool active = (u < 4) || (lane == 0);
        float2 p = make_float2(0.0f, 0.0f);
        if (active) {
            float2 bp = g_blkprefP[(size_t)b * NPAIR + k];
            float2 sp = g_subprefP[((size_t)b * NWARP + w) * NPAIR + k];
            p.x = fmaxf(dw * bp.x, sp.x);
            p.y = fmaxf(dw * bp.y, sp.y);
        }
        rA[u] = p.x; rB[u] = p.y;
    }

    int f0 = b * FPB + w * SUBF;
    const float scale = 1.0f / 256.0f;
#pragma unroll
    for (int i = 0; i < SUBF; i++) {
        int f = f0 + i;
        if (f >= NFRAMES) break;
        size_t base = (size_t)f * NPAIR;

#pragma unroll
        for (int u = 0; u < 5; u++) {
            int k = (u < 4) ? 32 * u + lane : 128;
            bool active = (u < 4) || (lane == 0);
            if (active) {
                float4 c = g_pair[base + k];
                float2 E = make_float2(c.x, c.y);
                float2 P = make_float2(c.z, c.w);
                float ax = E.x + P.x, ay = E.y + P.y;
                float bx = E.x - P.x, by = E.y - P.y;
                float ma2 = ax * ax + ay * ay;
                float mb2 = bx * bx + by * by;
                float ra = fmaxf(DECAYF * rA[u], sqrtf(ma2)); rA[u] = ra;
                float rb = fmaxf(DECAYF * rB[u], sqrtf(mb2)); rB[u] = rb;
                float ga = ma2 / (fmaxf(0.5f * ra * ra, 1e-8f) + ma2);
                float gb = mb2 / (fmaxf(0.5f * rb * rb, 1e-8f) + mb2);
                float s = 0.5f * (ga + gb), md = 0.5f * (ga - gb);
                float2 ze = make_float2(s * E.x + md * P.x, s * E.y + md * P.y);
                float2 d2 = make_float2(md * E.x + s * P.x, md * E.y + s * P.y);
                float2 tw = sm->W[k];
                // zo = conj(W^k) * d2
                float2 zo = make_float2(tw.x * d2.x + tw.y * d2.y,
                                        tw.x * d2.y - tw.y * d2.x);
                // V[k] = conj(ze + i*zo); V[256-k] = ze - i*zo
                Zs[SWZ(k)] = make_float2(ze.x - zo.y, -(ze.y + zo.x));
                if (k >= 1 && k <= 127)
                    Zs[SWZ(256 - k)] = make_float2(ze.x + zo.y, ze.y - zo.x);
            }
        }
        __syncwarp();

        float2 r[8];
#pragma unroll
        for (int j = 0; j < 8; j++) r[j] = Zs[SWZ(32 * j + lane)];
        warp_fft256(r, lane, sm->W);

        // stage time-domain pairs into Z (swizzled scatter, conflict-free)
#pragma unroll
        for (int j = 0; j < 8; j++) {
            int pos = brev8(32 * j + lane);
            Zs[SWZ(pos)] = make_float2(r[j].x, -r[j].y);
        }
        __syncwarp();

        // linear window+scale+accumulate into warp-private OLA buffer
        float2* acc2 = sm->acc[w] + i * (HOP / 2);
#pragma unroll
        for (int j = 0; j < 8; j++) {
            int p = 32 * j + lane;
            float2 v = Zs[SWZ(p)];
            float2 w2 = sm->win2[p];
            float2 cur = acc2[p];
            cur.x = fmaf(v.x * scale, w2.x, cur.x);
            cur.y = fmaf(v.y * scale, w2.y, cur.y);
            acc2[p] = cur;
        }
        __syncwarp();
    }
    __syncthreads();

    // combine warp regions & write normalized interior output.
    // Warp w covers samples [w*256, w*256+640): up to 3 contributors per sample.
    // Interior: exactly 4 overlapping Hann frames -> sum win^2 = 1.5.
    const float INV_NORM = 1.0f / 1.5f;
    int t0 = b * BLK_SPAN;
    const float* accf = (const float*)sm->acc;
    for (int s = t; s < BLK_SPAN; s += 512) {
        int wo = s >> 8;          // 256 samples per warp region
        int off = s & 255;
        float val = accf[wo * ACC_SPAN + off];
        if (wo > 0 && off < OVER) val += accf[(wo - 1) * ACC_SPAN + 256 + off];
        if (wo > 1 && off < OVER - 256) val += accf[(wo - 2) * ACC_SPAN + 512 + off];
        if (s < OVER) {
            g_head[(size_t)b * OVER + s] = val;
        } else {
            int tt = t0 + s;
            if (tt >= PAD && tt < PAD + T_SAMPLES) out[tt - PAD] = val * INV_NORM;
        }
    }
    // tail: contributions beyond this block's span, consumed by next block's head
    if (t < OVER) {
        float tv = accf[(NWARP - 1) * ACC_SPAN + 256 + t];
        if (t < OVER - 256) tv += accf[(NWARP - 2) * ACC_SPAN + 512 + t];
        g_tail[(size_t)b * OVER + t] = tv;
    }
}

// ---------------- fixup: block-boundary samples (general win^2 loop) ----------------
__global__ __launch_bounds__(384) void fixup(float* __restrict__ out) {
    int b = blockIdx.x;
    int i = threadIdx.x;
    int tt = b * BLK_SPAN + i;
    float val = g_head[(size_t)b * OVER + i] + (b > 0 ? g_tail[(size_t)(b - 1) * OVER + i] : 0.0f);
    if (tt >= PAD && tt < PAD + T_SAMPLES) {
        int fmax_ = tt >> 7; if (fmax_ > NFRAMES - 1) fmax_ = NFRAMES - 1;
        int fmin_ = (tt - OVER) >> 7; if (fmin_ < 0) fmin_ = 0;
        float ws = 0.0f;
        for (int fr = fmin_; fr <= fmax_; fr++) {
            float wv = g_win[tt - (fr << 7)];
            ws += wv * wv;
        }
        out[tt - PAD] = val / fmaxf(ws, 1e-11f);
    }
}

// ---------------- launch ----------------
extern "C" void kernel_launch(void* const* d_in, const int* in_sizes, int n_in,
                              void* d_out, int out_size) {
    const float* x = (const float*)d_in[0];
    float* out = (float*)d_out;

    static bool attr_done = false;
    if (!attr_done) {
        cudaFuncSetAttribute(phaseA, cudaFuncAttributeMaxDynamicSharedMemorySize,
                             (int)sizeof(SmemA));
        cudaFuncSetAttribute(phaseB, cudaFuncAttributeMaxDynamicSharedMemorySize,
                             (int)sizeof(SmemB));
        attr_done = true;
    }

    init_tables<<<1, 512>>>();
    phaseA<<<NBLKS, 512, sizeof(SmemA)>>>(x);
    midscanA<<<NSUP, 288>>>();
    midscanB<<<1, 288>>>();
    midscanC<<<NSUP, 288>>>();
    phaseB<<<NBLKS, 512, sizeof(SmemB)>>>(out);
    fixup<<<NBLKS, 384>>>(out);
}

// round 14
// speedup vs baseline: 1.0458x; 1.0369x over previous
#include <cuda_runtime.h>

#define T_SAMPLES 8388608
#define NFFT 512
#define HOP 128
#define PAD 256
#define NFRAMES 65537          // 1 + (T + 2*PAD - NFFT)/HOP
#define NPAIR 129              // mirror pairs (k, 256-k), k = 0..128
#define FPB 64                 // frames per block
#define NBLKS 1025             // ceil(NFRAMES / FPB)
#define NWARP 16
#define SUBF 4                 // frames per warp subchunk
#define BLK_SPAN (FPB * HOP)   // 8192
#define ACC_SPAN (SUBF * HOP + (NFFT - HOP))  // 896 floats
#define OVER (NFFT - HOP)      // 384
#define NSUP 41                // superchunks: 1025 = 41 * 25
#define SUPLEN 25
#define DECAYF 0.999f
#define PI_D 3.14159265358979323846

// XOR swizzle: kills bank conflicts on bit-reversed float2 scatters/gathers.
#define SWZ(p) ((p) ^ (((p) >> 4) & 0x0F))

// ---------------- global scratch ----------------
__device__ float4 g_pair[(size_t)NFRAMES * NPAIR];      // (E, P) per mirror pair, ~135MB
__device__ float2 g_subprefP[NBLKS * NWARP * NPAIR];    // within-block exclusive prefixes
__device__ float2 g_blkP[NBLKS * NPAIR];                // per-block inclusive summaries
__device__ float2 g_blkprefP[NBLKS * NPAIR];            // cross-block exclusive prefixes
__device__ float2 g_supP[NSUP * NPAIR];                 // superchunk inclusive totals
__device__ float2 g_supprefP[NSUP * NPAIR];             // superchunk exclusive prefixes
__device__ float  g_head[NBLKS * OVER];
__device__ float  g_tail[NBLKS * OVER];
__device__ float2 g_W512[512];
__device__ float  g_win[512];
__device__ float  g_D4, g_D64, g_D1600;
__device__ float  g_Dpow4[NWARP];                       // DECAY^(4*w)

__device__ __forceinline__ float2 cmul(float2 a, float2 b) {
    return make_float2(a.x * b.x - a.y * b.y, a.x * b.y + a.y * b.x);
}
__device__ __forceinline__ float2 csub(float2 a, float2 b) {
    return make_float2(a.x - b.x, a.y - b.y);
}
__device__ __forceinline__ float2 cadd(float2 a, float2 b) {
    return make_float2(a.x + b.x, a.y + b.y);
}
__device__ __forceinline__ int brev8(int x) { return (int)(__brev((unsigned)x) >> 24); }

// ---------------- tables ----------------
__global__ void init_tables() {
    int i = threadIdx.x;  // 512 threads
    double ang = -2.0 * PI_D * (double)i / 512.0;
    g_W512[i] = make_float2((float)cos(ang), (float)sin(ang));
    g_win[i]  = (float)(0.5 * (1.0 - cos(2.0 * PI_D * (double)i / 512.0)));
    if (i < NWARP) g_Dpow4[i] = (float)pow((double)DECAYF, 4.0 * i);
    if (i == 0) {
        g_D4    = (float)pow((double)DECAYF, 4.0);
        g_D64   = (float)pow((double)DECAYF, 64.0);
        g_D1600 = (float)pow((double)DECAYF, 1600.0);
    }
}

// ---------------- warp-level 256-pt complex FFT (DIF radix-2, slim butterflies) ----------------
__device__ __forceinline__ void warp_fft256(float2 r[8], int lane, const float2* s_W) {
#pragma unroll
    for (int j = 0; j < 4; j++) {
        float2 a = r[j], b = r[j + 4];
        float2 w = s_W[2 * (32 * j + lane)];
        r[j] = cadd(a, b);
        r[j + 4] = cmul(csub(a, b), w);
    }
#pragma unroll
    for (int half = 0; half < 2; half++) {
#pragma unroll
        for (int j = 0; j < 2; j++) {
            int lo = half * 4 + j;
            float2 a = r[lo], b = r[lo + 2];
            float2 w = s_W[4 * (32 * j + lane)];
            r[lo] = cadd(a, b);
            r[lo + 2] = cmul(csub(a, b), w);
        }
    }
    {
        float2 w = s_W[8 * lane];
#pragma unroll
        for (int q = 0; q < 4; q++) {
            int lo = 2 * q;
            float2 a = r[lo], b = r[lo + 1];
            r[lo] = cadd(a, b);
            r[lo + 1] = cmul(csub(a, b), w);
        }
    }
#pragma unroll
    for (int sidx = 0; sidx < 4; sidx++) {
        const int m = 16 >> sidx;
        bool up = (lane & m) != 0;
        float sgn = up ? -1.0f : 1.0f;
        float2 tw = s_W[(256 / m) * (lane & (m - 1))];
        float2 w_eff = up ? tw : make_float2(1.0f, 0.0f);
#pragma unroll
        for (int j = 0; j < 8; j++) {
            float ox = __shfl_xor_sync(0xffffffffu, r[j].x, m);
            float oy = __shfl_xor_sync(0xffffffffu, r[j].y, m);
            float sx = fmaf(sgn, r[j].x, ox);
            float sy = fmaf(sgn, r[j].y, oy);
            r[j] = cmul(make_float2(sx, sy), w_eff);
        }
    }
    {
        float sgn = (lane & 1) ? -1.0f : 1.0f;
#pragma unroll
        for (int j = 0; j < 8; j++) {
            float ox = __shfl_xor_sync(0xffffffffu, r[j].x, 1);
            float oy = __shfl_xor_sync(0xffffffffu, r[j].y, 1);
            r[j] = make_float2(fmaf(sgn, r[j].x, ox), fmaf(sgn, r[j].y, oy));
        }
    }
}

// ---------------- frame load with hoisted window regs ----------------
__device__ __forceinline__ void load_frame(const float* __restrict__ x, int f, int lane,
                                           const float2 win2p[8], float2 r[8]) {
    int p0 = f * HOP - PAD;
    if (p0 >= 0 && p0 + NFFT <= T_SAMPLES) {
        const float2* xv = (const float2*)(x + p0);
#pragma unroll
        for (int j = 0; j < 8; j++) {
            int k = 32 * j + lane;
            float2 v = xv[k];
            r[j] = make_float2(v.x * win2p[j].x, v.y * win2p[j].y);
        }
    } else {
#pragma unroll
        for (int j = 0; j < 8; j++) {
            int k = 32 * j + lane;
            int pa = p0 + 2 * k, pb = pa + 1;
            if (pa < 0) pa = -pa; else if (pa >= T_SAMPLES) pa = 2 * T_SAMPLES - 2 - pa;
            if (pb < 0) pb = -pb; else if (pb >= T_SAMPLES) pb = 2 * T_SAMPLES - 2 - pb;
            r[j] = make_float2(x[pa] * win2p[j].x, x[pb] * win2p[j].y);
        }
    }
}

// ---------------- smem layouts ----------------
struct SmemA {
    float2 W[512];
    float2 win2[256];
    float2 Z[NWARP][256];
    float2 subP[NWARP][NPAIR];
};
struct SmemB {
    float2 W[512];
    float2 win2[256];
    float2 Z[NWARP][256];
    float2 acc[NWARP][ACC_SPAN / 2];   // 448 float2 per warp
};

// ---------------- phase A: FFT -> paired (E,P) spectrum + runmax summaries ----------------
__global__ __launch_bounds__(512, 2) void phaseA(const float* __restrict__ x) {
    extern __shared__ char raw[];
    SmemA* sm = (SmemA*)raw;
    int t = threadIdx.x, lane = t & 31, w = t >> 5, b = blockIdx.x;
    sm->W[t] = g_W512[t];
    if (t < 256) sm->win2[t] = make_float2(g_win[2 * t], g_win[2 * t + 1]);
    __syncthreads();

    float2* Zs = sm->Z[w];
    float2 win2p[8];
#pragma unroll
    for (int j = 0; j < 8; j++) win2p[j] = sm->win2[32 * j + lane];

    float rA[5], rB[5];
#pragma unroll
    for (int u = 0; u < 5; u++) { rA[u] = 0.0f; rB[u] = 0.0f; }

    int f0 = b * FPB + w * SUBF;
#pragma unroll
    for (int i = 0; i < SUBF; i++) {
        int f = f0 + i;
        if (f >= NFRAMES) break;
        float2 r[8];
        load_frame(x, f, lane, win2p, r);
        warp_fft256(r, lane, sm->W);
#pragma unroll
        for (int j = 0; j < 8; j++) Zs[SWZ(brev8(32 * j + lane))] = r[j];
        __syncwarp();

        size_t base = (size_t)f * NPAIR;
#pragma unroll
        for (int u = 0; u < 5; u++) {
            int k = (u < 4) ? 32 * u + lane : 128;
            bool active = (u < 4) || (lane == 0);
            if (active) {
                float2 zk = Zs[SWZ(k)];
                float2 zm = Zs[SWZ((256 - k) & 255)];
                float2 E = make_float2(0.5f * (zk.x + zm.x), 0.5f * (zk.y - zm.y));
                float2 d = make_float2(0.5f * (zk.x - zm.x), 0.5f * (zk.y + zm.y));
                float2 mid = make_float2(d.y, -d.x);          // -i * d
                float2 P = cmul(sm->W[k], mid);
                g_pair[base + k] = make_float4(E.x, E.y, P.x, P.y);
                float ax = E.x + P.x, ay = E.y + P.y;
                float bx = E.x - P.x, by = E.y - P.y;
                rA[u] = fmaxf(DECAYF * rA[u], sqrtf(ax * ax + ay * ay));
                rB[u] = fmaxf(DECAYF * rB[u], sqrtf(bx * bx + by * by));
            }
        }
        __syncwarp();
    }
#pragma unroll
    for (int u = 0; u < 5; u++) {
        int k = (u < 4) ? 32 * u + lane : 128;
        bool active = (u < 4) || (lane == 0);
        if (active) sm->subP[w][k] = make_float2(rA[u], rB[u]);
    }
    __syncthreads();
    // block summary + within-block exclusive prefixes (float view width 2*NPAIR = 258)
    if (t < 2 * NPAIR) {
        float D4 = g_D4;
        const float* subF = (const float*)sm->subP;
        float carry = 0.0f;
#pragma unroll
        for (int j = 0; j < NWARP; j++) {
            ((float*)g_subprefP)[(b * NWARP + j) * 2 * NPAIR + t] = carry;
            carry = fmaxf(D4 * carry, subF[j * 2 * NPAIR + t]);
        }
        ((float*)g_blkP)[b * 2 * NPAIR + t] = carry;
    }
}

// ---------------- 3-level cross-block scan (no grid barrier, no atomics) ----------------
__global__ __launch_bounds__(288) void midscanA() {
    int t = threadIdx.x;
    if (t >= 2 * NPAIR) return;
    int s = blockIdx.x;
    const float* blkF = (const float*)g_blkP;
    float D64 = g_D64;
    float v[SUPLEN];
#pragma unroll
    for (int j = 0; j < SUPLEN; j++) v[j] = blkF[(s * SUPLEN + j) * 2 * NPAIR + t];
    float carry = 0.0f;
#pragma unroll
    for (int j = 0; j < SUPLEN; j++) carry = fmaxf(D64 * carry, v[j]);
    ((float*)g_supP)[s * 2 * NPAIR + t] = carry;
}

__global__ __launch_bounds__(288) void midscanB() {
    int t = threadIdx.x;
    if (t >= 2 * NPAIR) return;
    const float* supF = (const float*)g_supP;
    float D1600 = g_D1600;
    float v[NSUP];
#pragma unroll
    for (int s = 0; s < NSUP; s++) v[s] = supF[s * 2 * NPAIR + t];
    float carry = 0.0f;
#pragma unroll
    for (int s = 0; s < NSUP; s++) {
        ((float*)g_supprefP)[s * 2 * NPAIR + t] = carry;
        carry = fmaxf(D1600 * carry, v[s]);
    }
}

__global__ __launch_bounds__(288) void midscanC() {
    int t = threadIdx.x;
    if (t >= 2 * NPAIR) return;
    int s = blockIdx.x;
    const float* blkF = (const float*)g_blkP;
    float D64 = g_D64;
    float v[SUPLEN];
#pragma unroll
    for (int j = 0; j < SUPLEN; j++) v[j] = blkF[(s * SUPLEN + j) * 2 * NPAIR + t];
    float carry = ((const float*)g_supprefP)[s * 2 * NPAIR + t];
#pragma unroll
    for (int j = 0; j < SUPLEN; j++) {
        ((float*)g_blkprefP)[(s * SUPLEN + j) * 2 * NPAIR + t] = carry;
        carry = fmaxf(D64 * carry, v[j]);
    }
}

// ---------------- phase B: gain (reg-direct), inverse FFT, staged linear OLA ----------------
__global__ __launch_bounds__(512, 2) void phaseB(float* __restrict__ out) {
    extern __shared__ char raw[];
    SmemB* sm = (SmemB*)raw;
    int t = threadIdx.x, lane = t & 31, w = t >> 5, b = blockIdx.x;
    sm->W[t] = g_W512[t];
    if (t < 256) sm->win2[t] = make_float2(g_win[2 * t], g_win[2 * t + 1]);
    for (int i = t; i < NWARP * (ACC_SPAN / 2); i += 512)
        ((float2*)sm->acc)[i] = make_float2(0.0f, 0.0f);
    __syncthreads();

    float2* Zs = sm->Z[w];
    // hoisted window regs (linear positions 32j+lane, for OLA accumulate)
    float2 win2p[8];
#pragma unroll
    for (int j = 0; j < 8; j++) win2p[j] = sm->win2[32 * j + lane];

    float dw = g_Dpow4[w];
    float rA[5], rB[5];
    // running max init: r = max(D^(4w) * blockprefix, within-block prefix)
#pragma unroll
    for (int u = 0; u < 5; u++) {
        int k = (u < 4) ? 32 * u + lane : 128;
        bool active = (u < 4) || (lane == 0);
        float2 p = make_float2(0.0f, 0.0f);
        if (active) {
            float2 bp = g_blkprefP[b * NPAIR + k];
            float2 sp = g_subprefP[(b * NWARP + w) * NPAIR + k];
            p.x = fmaxf(dw * bp.x, sp.x);
            p.y = fmaxf(dw * bp.y, sp.y);
        }
        rA[u] = p.x; rB[u] = p.y;
    }

    int f0 = b * FPB + w * SUBF;
    const float scale = 1.0f / 256.0f;
#pragma unroll
    for (int i = 0; i < SUBF; i++) {
        int f = f0 + i;
        if (f >= NFRAMES) break;
        size_t base = (size_t)f * NPAIR;

        // gain + repack: direct half V[k] kept in registers; mirror half -> smem
        float2 vreg[5];
#pragma unroll
        for (int u = 0; u < 5; u++) {
            int k = (u < 4) ? 32 * u + lane : 128;
            bool active = (u < 4) || (lane == 0);
            if (active) {
                float4 c = g_pair[base + k];
                float2 E = make_float2(c.x, c.y);
                float2 P = make_float2(c.z, c.w);
                float ax = E.x + P.x, ay = E.y + P.y;
                float bx = E.x - P.x, by = E.y - P.y;
                float ma2 = ax * ax + ay * ay;
                float mb2 = bx * bx + by * by;
                float ra = fmaxf(DECAYF * rA[u], sqrtf(ma2)); rA[u] = ra;
                float rb = fmaxf(DECAYF * rB[u], sqrtf(mb2)); rB[u] = rb;
                float ga = ma2 / (fmaxf(0.5f * ra * ra, 1e-8f) + ma2);
                float gb = mb2 / (fmaxf(0.5f * rb * rb, 1e-8f) + mb2);
                float s = 0.5f * (ga + gb), md = 0.5f * (ga - gb);
                float2 ze = make_float2(s * E.x + md * P.x, s * E.y + md * P.y);
                float2 d2 = make_float2(md * E.x + s * P.x, md * E.y + s * P.y);
                float2 tw = sm->W[k];
                // zo = conj(W^k) * d2
                float2 zo = make_float2(tw.x * d2.x + tw.y * d2.y,
                                        tw.x * d2.y - tw.y * d2.x);
                vreg[u] = make_float2(ze.x - zo.y, -(ze.y + zo.x));   // V[k]
                if (k >= 1 && k <= 127)                               // V[256-k]
                    Zs[SWZ(256 - k)] = make_float2(ze.x + zo.y, ze.y - zo.x);
            }
        }
        __syncwarp();

        // FFT input: j=0..3 direct from regs; j=4..7 from mirror half
        float2 r[8];
#pragma unroll
        for (int j = 0; j < 4; j++) r[j] = vreg[j];
        r[4] = (lane == 0) ? vreg[4] : Zs[SWZ(128 + lane)];
        r[5] = Zs[SWZ(160 + lane)];
        r[6] = Zs[SWZ(192 + lane)];
        r[7] = Zs[SWZ(224 + lane)];
        warp_fft256(r, lane, sm->W);

        // stage time-domain pairs into Z (swizzled scatter, conflict-free)
#pragma unroll
        for (int j = 0; j < 8; j++) {
            int pos = brev8(32 * j + lane);
            Zs[SWZ(pos)] = make_float2(r[j].x, -r[j].y);
        }
        __syncwarp();

        // linear window+scale+accumulate into warp-private OLA buffer
        float2* acc2 = sm->acc[w] + i * (HOP / 2);
#pragma unroll
        for (int j = 0; j < 8; j++) {
            int p = 32 * j + lane;
            float2 v = Zs[SWZ(p)];
            float2 cur = acc2[p];
            cur.x = fmaf(v.x * scale, win2p[j].x, cur.x);
            cur.y = fmaf(v.y * scale, win2p[j].y, cur.y);
            acc2[p] = cur;
        }
        __syncwarp();
    }
    __syncthreads();

    // combine warp regions & write normalized interior output.
    // Interior: exactly 4 overlapping Hann frames -> sum win^2 = 1.5.
    const float INV_NORM = 1.0f / 1.5f;
    int t0 = b * BLK_SPAN;
    const float* accf = (const float*)sm->acc;
    for (int s = t; s < BLK_SPAN; s += 512) {
        int wo = s >> 9;          // 512 samples per warp region
        int off = s & 511;
        float val = accf[wo * ACC_SPAN + off];
        if (off < OVER && wo > 0) val += accf[(wo - 1) * ACC_SPAN + 512 + off];
        if (s < OVER) {
            g_head[b * OVER + s] = val;
        } else {
            int tt = t0 + s;
            if (tt >= PAD && tt < PAD + T_SAMPLES) out[tt - PAD] = val * INV_NORM;
        }
    }
    if (t < OVER) g_tail[b * OVER + t] = accf[(NWARP - 1) * ACC_SPAN + 512 + t];
}

// ---------------- fixup: block-boundary samples (general win^2 loop) ----------------
__global__ __launch_bounds__(384) void fixup(float* __restrict__ out) {
    int b = blockIdx.x;
    int i = threadIdx.x;
    int tt = b * BLK_SPAN + i;
    float val = g_head[b * OVER + i] + (b > 0 ? g_tail[(b - 1) * OVER + i] : 0.0f);
    if (tt >= PAD && tt < PAD + T_SAMPLES) {
        int fmax_ = tt >> 7; if (fmax_ > NFRAMES - 1) fmax_ = NFRAMES - 1;
        int fmin_ = (tt - OVER) >> 7; if (fmin_ < 0) fmin_ = 0;
        float ws = 0.0f;
        for (int fr = fmin_; fr <= fmax_; fr++) {
            float wv = g_win[tt - (fr << 7)];
            ws += wv * wv;
        }
        out[tt - PAD] = val / fmaxf(ws, 1e-11f);
    }
}

// ---------------- launch ----------------
extern "C" void kernel_launch(void* const* d_in, const int* in_sizes, int n_in,
                              void* d_out, int out_size) {
    const float* x = (const float*)d_in[0];
    float* out = (float*)d_out;

    static bool attr_done = false;
    if (!attr_done) {
        cudaFuncSetAttribute(phaseA, cudaFuncAttributeMaxDynamicSharedMemorySize,
                             (int)sizeof(SmemA));
        cudaFuncSetAttribute(phaseB, cudaFuncAttributeMaxDynamicSharedMemorySize,
                             (int)sizeof(SmemB));
        attr_done = true;
    }

    init_tables<<<1, 512>>>();
    phaseA<<<NBLKS, 512, sizeof(SmemA)>>>(x);
    midscanA<<<NSUP, 288>>>();
    midscanB<<<1, 288>>>();
    midscanC<<<NSUP, 288>>>();
    phaseB<<<NBLKS, 512, sizeof(SmemB)>>>(out);
    fixup<<<NBLKS, 384>>>(out);
}

// round 16
// speedup vs baseline: 1.0778x; 1.0306x over previous
#include <cuda_runtime.h>

#define T_SAMPLES 8388608
#define NFFT 512
#define HOP 128
#define PAD 256
#define NFRAMES 65537          // 1 + (T + 2*PAD - NFFT)/HOP
#define NPAIR 129              // mirror pairs (k, 256-k), k = 0..128
#define FPB 64                 // frames per block
#define NBLKS 1025             // ceil(NFRAMES / FPB)
#define NWARP 16
#define SUBF 4                 // frames per warp subchunk
#define BLK_SPAN (FPB * HOP)   // 8192
#define ACC_SPAN (SUBF * HOP + (NFFT - HOP))  // 896 floats
#define OVER (NFFT - HOP)      // 384
#define NSUP 41                // superchunks: 1025 = 41 * 25
#define SUPLEN 25
#define DECAYF 0.999f
#define PI_D 3.14159265358979323846

// XOR swizzle: kills bank conflicts on bit-reversed float2 scatters/gathers.
#define SWZ(p) ((p) ^ (((p) >> 4) & 0x0F))

// ---------------- global scratch ----------------
__device__ float4 g_pair[(size_t)NFRAMES * NPAIR];      // (E, P) per mirror pair, ~135MB
__device__ float2 g_subprefP[NBLKS * NWARP * NPAIR];    // within-block exclusive prefixes
__device__ float2 g_blkP[NBLKS * NPAIR];                // per-block inclusive summaries
__device__ float2 g_blkprefP[NBLKS * NPAIR];            // cross-block exclusive prefixes
__device__ float2 g_supP[NSUP * NPAIR];                 // superchunk inclusive totals
__device__ float  g_head[NBLKS * OVER];
__device__ float  g_tail[NBLKS * OVER];
__device__ float2 g_W512[512];
__device__ float  g_win[512];
__device__ float  g_D4, g_D64, g_D1600;
__device__ float  g_Dpow4[NWARP];                       // DECAY^(4*w)

__device__ __forceinline__ float2 cmul(float2 a, float2 b) {
    return make_float2(a.x * b.x - a.y * b.y, a.x * b.y + a.y * b.x);
}
__device__ __forceinline__ float2 csub(float2 a, float2 b) {
    return make_float2(a.x - b.x, a.y - b.y);
}
__device__ __forceinline__ float2 cadd(float2 a, float2 b) {
    return make_float2(a.x + b.x, a.y + b.y);
}
__device__ __forceinline__ int brev8(int x) { return (int)(__brev((unsigned)x) >> 24); }

// hoisted per-thread twiddles for the shuffle stages (loop-invariant)
struct FftTw {
    float2 wc;    // s_W[8*lane]      (in-register stage C)
    float2 t16;   // s_W[16*(lane&15)]
    float2 t8;    // s_W[32*(lane&7)]
    float2 t4;    // s_W[64*(lane&3)]
};

__device__ __forceinline__ FftTw make_tw(int lane, const float2* s_W) {
    FftTw tw;
    tw.wc  = s_W[8 * lane];
    tw.t16 = s_W[16 * (lane & 15)];
    tw.t8  = s_W[32 * (lane & 7)];
    tw.t4  = s_W[64 * (lane & 3)];
    return tw;
}

// ---------------- tables ----------------
__global__ void init_tables() {
    int i = threadIdx.x;  // 512 threads
    double ang = -2.0 * PI_D * (double)i / 512.0;
    g_W512[i] = make_float2((float)cos(ang), (float)sin(ang));
    g_win[i]  = (float)(0.5 * (1.0 - cos(2.0 * PI_D * (double)i / 512.0)));
    if (i < NWARP) g_Dpow4[i] = (float)pow((double)DECAYF, 4.0 * i);
    if (i == 0) {
        g_D4    = (float)pow((double)DECAYF, 4.0);
        g_D64   = (float)pow((double)DECAYF, 64.0);
        g_D1600 = (float)pow((double)DECAYF, 1600.0);
    }
}

// ---------------- warp-level 256-pt complex FFT (DIF radix-2, hoisted twiddles) ----------------
__device__ __forceinline__ void warp_fft256(float2 r[8], int lane, const float2* s_W,
                                            const FftTw& tw) {
#pragma unroll
    for (int j = 0; j < 4; j++) {
        float2 a = r[j], b = r[j + 4];
        float2 w = s_W[2 * (32 * j + lane)];
        r[j] = cadd(a, b);
        r[j + 4] = cmul(csub(a, b), w);
    }
#pragma unroll
    for (int half = 0; half < 2; half++) {
#pragma unroll
        for (int j = 0; j < 2; j++) {
            int lo = half * 4 + j;
            float2 a = r[lo], b = r[lo + 2];
            float2 w = s_W[4 * (32 * j + lane)];
            r[lo] = cadd(a, b);
            r[lo + 2] = cmul(csub(a, b), w);
        }
    }
    {
#pragma unroll
        for (int q = 0; q < 4; q++) {
            int lo = 2 * q;
            float2 a = r[lo], b = r[lo + 1];
            r[lo] = cadd(a, b);
            r[lo + 1] = cmul(csub(a, b), tw.wc);
        }
    }
    // shuffle stages m = 16, 8, 4 (hoisted twiddles), m = 2 (constant), m = 1 (add/sub)
#pragma unroll
    for (int sidx = 0; sidx < 3; sidx++) {
        const int m = 16 >> sidx;
        bool up = (lane & m) != 0;
        float sgn = up ? -1.0f : 1.0f;
        float2 twv = (sidx == 0) ? tw.t16 : (sidx == 1) ? tw.t8 : tw.t4;
        float2 w_eff = up ? twv : make_float2(1.0f, 0.0f);
#pragma unroll
        for (int j = 0; j < 8; j++) {
            float ox = __shfl_xor_sync(0xffffffffu, r[j].x, m);
            float oy = __shfl_xor_sync(0xffffffffu, r[j].y, m);
            float sx = fmaf(sgn, r[j].x, ox);
            float sy = fmaf(sgn, r[j].y, oy);
            r[j] = cmul(make_float2(sx, sy), w_eff);
        }
    }
    {
        // m = 2 stage: twiddle index is (lane & 1): s_W[128*(lane&1)] = (0,-1) iff lane&1.
        // Butterfly role (up) is (lane & 2). Only up lanes multiply by their twiddle.
        const int m = 2;
        bool up = (lane & m) != 0;
        float sgn = up ? -1.0f : 1.0f;
        float2 twv = (lane & 1) ? make_float2(0.0f, -1.0f) : make_float2(1.0f, 0.0f);
        float2 w_eff = up ? twv : make_float2(1.0f, 0.0f);
#pragma unroll
        for (int j = 0; j < 8; j++) {
            float ox = __shfl_xor_sync(0xffffffffu, r[j].x, m);
            float oy = __shfl_xor_sync(0xffffffffu, r[j].y, m);
            float sx = fmaf(sgn, r[j].x, ox);
            float sy = fmaf(sgn, r[j].y, oy);
            r[j] = cmul(make_float2(sx, sy), w_eff);
        }
    }
    {
        float sgn = (lane & 1) ? -1.0f : 1.0f;
#pragma unroll
        for (int j = 0; j < 8; j++) {
            float ox = __shfl_xor_sync(0xffffffffu, r[j].x, 1);
            float oy = __shfl_xor_sync(0xffffffffu, r[j].y, 1);
            r[j] = make_float2(fmaf(sgn, r[j].x, ox), fmaf(sgn, r[j].y, oy));
        }
    }
}

// ---------------- frame load with hoisted window regs ----------------
__device__ __forceinline__ void load_frame(const float* __restrict__ x, int f, int lane,
                                           const float2 win2p[8], float2 r[8]) {
    int p0 = f * HOP - PAD;
    if (p0 >= 0 && p0 + NFFT <= T_SAMPLES) {
        const float2* xv = (const float2*)(x + p0);
#pragma unroll
        for (int j = 0; j < 8; j++) {
            int k = 32 * j + lane;
            float2 v = xv[k];
            r[j] = make_float2(v.x * win2p[j].x, v.y * win2p[j].y);
        }
    } else {
#pragma unroll
        for (int j = 0; j < 8; j++) {
            int k = 32 * j + lane;
            int pa = p0 + 2 * k, pb = pa + 1;
            if (pa < 0) pa = -pa; else if (pa >= T_SAMPLES) pa = 2 * T_SAMPLES - 2 - pa;
            if (pb < 0) pb = -pb; else if (pb >= T_SAMPLES) pb = 2 * T_SAMPLES - 2 - pb;
            r[j] = make_float2(x[pa] * win2p[j].x, x[pb] * win2p[j].y);
        }
    }
}

// ---------------- smem layouts ----------------
struct SmemA {
    float2 W[512];
    float2 win2[256];
    float2 Z[NWARP][256];
    float2 subP[NWARP][NPAIR];
};
struct SmemB {
    float2 W[512];
    float2 win2[256];
    float2 Z[NWARP][256];
    float2 acc[NWARP][ACC_SPAN / 2];   // 448 float2 per warp
};

// ---------------- phase A: FFT -> paired (E,P) spectrum + runmax summaries ----------------
__global__ __launch_bounds__(512, 2) void phaseA(const float* __restrict__ x) {
    extern __shared__ char raw[];
    SmemA* sm = (SmemA*)raw;
    int t = threadIdx.x, lane = t & 31, w = t >> 5, b = blockIdx.x;
    sm->W[t] = g_W512[t];
    if (t < 256) sm->win2[t] = make_float2(g_win[2 * t], g_win[2 * t + 1]);
    __syncthreads();

    float2* Zs = sm->Z[w];
    FftTw tw = make_tw(lane, sm->W);
    float2 win2p[8];
#pragma unroll
    for (int j = 0; j < 8; j++) win2p[j] = sm->win2[32 * j + lane];

    float rA[5], rB[5];
#pragma unroll
    for (int u = 0; u < 5; u++) { rA[u] = 0.0f; rB[u] = 0.0f; }

    int f0 = b * FPB + w * SUBF;
#pragma unroll
    for (int i = 0; i < SUBF; i++) {
        int f = f0 + i;
        if (f >= NFRAMES) break;
        float2 r[8];
        load_frame(x, f, lane, win2p, r);
        warp_fft256(r, lane, sm->W, tw);
#pragma unroll
        for (int j = 0; j < 8; j++) Zs[SWZ(brev8(32 * j + lane))] = r[j];
        __syncwarp();

        size_t base = (size_t)f * NPAIR;
#pragma unroll
        for (int u = 0; u < 5; u++) {
            int k = (u < 4) ? 32 * u + lane : 128;
            bool active = (u < 4) || (lane == 0);
            if (active) {
                float2 zk = Zs[SWZ(k)];
                float2 zm = Zs[SWZ((256 - k) & 255)];
                float2 E = make_float2(0.5f * (zk.x + zm.x), 0.5f * (zk.y - zm.y));
                float2 d = make_float2(0.5f * (zk.x - zm.x), 0.5f * (zk.y + zm.y));
                float2 mid = make_float2(d.y, -d.x);          // -i * d
                float2 P = cmul(sm->W[k], mid);
                g_pair[base + k] = make_float4(E.x, E.y, P.x, P.y);
                float ax = E.x + P.x, ay = E.y + P.y;
                float bx = E.x - P.x, by = E.y - P.y;
                rA[u] = fmaxf(DECAYF * rA[u], sqrtf(ax * ax + ay * ay));
                rB[u] = fmaxf(DECAYF * rB[u], sqrtf(bx * bx + by * by));
            }
        }
        __syncwarp();
    }
#pragma unroll
    for (int u = 0; u < 5; u++) {
        int k = (u < 4) ? 32 * u + lane : 128;
        bool active = (u < 4) || (lane == 0);
        if (active) sm->subP[w][k] = make_float2(rA[u], rB[u]);
    }
    __syncthreads();
    // block summary + within-block exclusive prefixes (float view width 2*NPAIR = 258)
    if (t < 2 * NPAIR) {
        float D4 = g_D4;
        const float* subF = (const float*)sm->subP;
        float carry = 0.0f;
#pragma unroll
        for (int j = 0; j < NWARP; j++) {
            ((float*)g_subprefP)[(b * NWARP + j) * 2 * NPAIR + t] = carry;
            carry = fmaxf(D4 * carry, subF[j * 2 * NPAIR + t]);
        }
        ((float*)g_blkP)[b * 2 * NPAIR + t] = carry;
    }
}

// ---------------- 2-level cross-block scan (no grid barrier, no atomics) ----------------
__global__ __launch_bounds__(288) void midscanA() {
    int t = threadIdx.x;
    if (t >= 2 * NPAIR) return;
    int s = blockIdx.x;
    const float* blkF = (const float*)g_blkP;
    float D64 = g_D64;
    float v[SUPLEN];
#pragma unroll
    for (int j = 0; j < SUPLEN; j++) v[j] = blkF[(s * SUPLEN + j) * 2 * NPAIR + t];
    float carry = 0.0f;
#pragma unroll
    for (int j = 0; j < SUPLEN; j++) carry = fmaxf(D64 * carry, v[j]);
    ((float*)g_supP)[s * 2 * NPAIR + t] = carry;
}

// midscanC also folds the former midscanB: each block recomputes the superchunk
// exclusive prefix locally from g_supP (41x41 redundant, L2-hot, trivial).
__global__ __launch_bounds__(288) void midscanC() {
    int t = threadIdx.x;
    if (t >= 2 * NPAIR) return;
    int s = blockIdx.x;
    const float* blkF = (const float*)g_blkP;
    const float* supF = (const float*)g_supP;
    float D64 = g_D64, D1600 = g_D1600;
    // exclusive prefix over earlier superchunks (MLP-batched)
    float sv[NSUP];
#pragma unroll
    for (int ss = 0; ss < NSUP; ss++)
        sv[ss] = (ss < s) ? supF[ss * 2 * NPAIR + t] : 0.0f;
    float carry = 0.0f;
#pragma unroll
    for (int ss = 0; ss < NSUP; ss++)
        if (ss < s) carry = fmaxf(D1600 * carry, sv[ss]);
    // scan own 25 blocks
    float v[SUPLEN];
#pragma unroll
    for (int j = 0; j < SUPLEN; j++) v[j] = blkF[(s * SUPLEN + j) * 2 * NPAIR + t];
#pragma unroll
    for (int j = 0; j < SUPLEN; j++) {
        ((float*)g_blkprefP)[(s * SUPLEN + j) * 2 * NPAIR + t] = carry;
        carry = fmaxf(D64 * carry, v[j]);
    }
}

// ---------------- phase B: gain (reg-direct), inverse FFT, staged linear OLA ----------------
__global__ __launch_bounds__(512, 2) void phaseB(float* __restrict__ out) {
    extern __shared__ char raw[];
    SmemB* sm = (SmemB*)raw;
    int t = threadIdx.x, lane = t & 31, w = t >> 5, b = blockIdx.x;
    sm->W[t] = g_W512[t];
    if (t < 256) sm->win2[t] = make_float2(g_win[2 * t], g_win[2 * t + 1]);
    for (int i = t; i < NWARP * (ACC_SPAN / 2); i += 512)
        ((float2*)sm->acc)[i] = make_float2(0.0f, 0.0f);
    __syncthreads();

    float2* Zs = sm->Z[w];
    FftTw tw = make_tw(lane, sm->W);
    // hoisted window regs (linear positions 32j+lane, for OLA accumulate)
    float2 win2p[8];
#pragma unroll
    for (int j = 0; j < 8; j++) win2p[j] = sm->win2[32 * j + lane];

    float dw = g_Dpow4[w];
    float rA[5], rB[5];
    // running max init: r = max(D^(4w) * blockprefix, within-block prefix)
#pragma unroll
    for (int u = 0; u < 5; u++) {
        int k = (u < 4) ? 32 * u + lane : 128;
        bool active = (u < 4) || (lane == 0);
        float2 p = make_float2(0.0f, 0.0f);
        if (active) {
            float2 bp = g_blkprefP[b * NPAIR + k];
            float2 sp = g_subprefP[(b * NWARP + w) * NPAIR + k];
            p.x = fmaxf(dw * bp.x, sp.x);
            p.y = fmaxf(dw * bp.y, sp.y);
        }
        rA[u] = p.x; rB[u] = p.y;
    }

    int f0 = b * FPB + w * SUBF;
    const float scale = 1.0f / 256.0f;
#pragma unroll
    for (int i = 0; i < SUBF; i++) {
        int f = f0 + i;
        if (f >= NFRAMES) break;
        size_t base = (size_t)f * NPAIR;

        // gain + repack: direct half V[k] kept in registers; mirror half -> smem
        float2 vreg[5];
#pragma unroll
        for (int u = 0; u < 5; u++) {
            int k = (u < 4) ? 32 * u + lane : 128;
            bool active = (u < 4) || (lane == 0);
            if (active) {
                float4 c = g_pair[base + k];
                float2 E = make_float2(c.x, c.y);
                float2 P = make_float2(c.z, c.w);
                float ax = E.x + P.x, ay = E.y + P.y;
                float bx = E.x - P.x, by = E.y - P.y;
                float ma2 = ax * ax + ay * ay;
                float mb2 = bx * bx + by * by;
                float ra = fmaxf(DECAYF * rA[u], sqrtf(ma2)); rA[u] = ra;
                float rb = fmaxf(DECAYF * rB[u], sqrtf(mb2)); rB[u] = rb;
                float ga = ma2 / (fmaxf(0.5f * ra * ra, 1e-8f) + ma2);
                float gb = mb2 / (fmaxf(0.5f * rb * rb, 1e-8f) + mb2);
                float s = 0.5f * (ga + gb), md = 0.5f * (ga - gb);
                float2 ze = make_float2(s * E.x + md * P.x, s * E.y + md * P.y);
                float2 d2 = make_float2(md * E.x + s * P.x, md * E.y + s * P.y);
                float2 twk = sm->W[k];
                // zo = conj(W^k) * d2
                float2 zo = make_float2(twk.x * d2.x + twk.y * d2.y,
                                        twk.x * d2.y - twk.y * d2.x);
                vreg[u] = make_float2(ze.x - zo.y, -(ze.y + zo.x));   // V[k]
                if (k >= 1 && k <= 127)                               // V[256-k]
                    Zs[SWZ(256 - k)] = make_float2(ze.x + zo.y, ze.y - zo.x);
            }
        }
        __syncwarp();

        // FFT input: j=0..3 direct from regs; j=4..7 from mirror half
        float2 r[8];
#pragma unroll
        for (int j = 0; j < 4; j++) r[j] = vreg[j];
        r[4] = (lane == 0) ? vreg[4] : Zs[SWZ(128 + lane)];
        r[5] = Zs[SWZ(160 + lane)];
        r[6] = Zs[SWZ(192 + lane)];
        r[7] = Zs[SWZ(224 + lane)];
        warp_fft256(r, lane, sm->W, tw);

        // stage time-domain pairs into Z (swizzled scatter, conflict-free)
#pragma unroll
        for (int j = 0; j < 8; j++) {
            int pos = brev8(32 * j + lane);
            Zs[SWZ(pos)] = make_float2(r[j].x, -r[j].y);
        }
        __syncwarp();

        // linear window+scale+accumulate into warp-private OLA buffer
        float2* acc2 = sm->acc[w] + i * (HOP / 2);
#pragma unroll
        for (int j = 0; j < 8; j++) {
            int p = 32 * j + lane;
            float2 v = Zs[SWZ(p)];
            float2 cur = acc2[p];
            cur.x = fmaf(v.x * scale, win2p[j].x, cur.x);
            cur.y = fmaf(v.y * scale, win2p[j].y, cur.y);
            acc2[p] = cur;
        }
        __syncwarp();
    }
    __syncthreads();

    // combine warp regions & write normalized interior output.
    // Interior: exactly 4 overlapping Hann frames -> sum win^2 = 1.5.
    const float INV_NORM = 1.0f / 1.5f;
    int t0 = b * BLK_SPAN;
    const float* accf = (const float*)sm->acc;
    for (int s = t; s < BLK_SPAN; s += 512) {
        int wo = s >> 9;          // 512 samples per warp region
        int off = s & 511;
        float val = accf[wo * ACC_SPAN + off];
        if (off < OVER && wo > 0) val += accf[(wo - 1) * ACC_SPAN + 512 + off];
        if (s < OVER) {
            g_head[b * OVER + s] = val;
        } else {
            int tt = t0 + s;
            if (tt >= PAD && tt < PAD + T_SAMPLES) out[tt - PAD] = val * INV_NORM;
        }
    }
    if (t < OVER) g_tail[b * OVER + t] = accf[(NWARP - 1) * ACC_SPAN + 512 + t];
}

// ---------------- fixup: block-boundary samples (general win^2 loop) ----------------
__global__ __launch_bounds__(384) void fixup(float* __restrict__ out) {
    int b = blockIdx.x;
    int i = threadIdx.x;
    int tt = b * BLK_SPAN + i;
    float val = g_head[b * OVER + i] + (b > 0 ? g_tail[(b - 1) * OVER + i] : 0.0f);
    if (tt >= PAD && tt < PAD + T_SAMPLES) {
        int fmax_ = tt >> 7; if (fmax_ > NFRAMES - 1) fmax_ = NFRAMES - 1;
        int fmin_ = (tt - OVER) >> 7; if (fmin_ < 0) fmin_ = 0;
        float ws = 0.0f;
        for (int fr = fmin_; fr <= fmax_; fr++) {
            float wv = g_win[tt - (fr << 7)];
            ws += wv * wv;
        }
        out[tt - PAD] = val / fmaxf(ws, 1e-11f);
    }
}

// ---------------- launch ----------------
extern "C" void kernel_launch(void* const* d_in, const int* in_sizes, int n_in,
                              void* d_out, int out_size) {
    const float* x = (const float*)d_in[0];
    float* out = (float*)d_out;

    static bool attr_done = false;
    if (!attr_done) {
        cudaFuncSetAttribute(phaseA, cudaFuncAttributeMaxDynamicSharedMemorySize,
                             (int)sizeof(SmemA));
        cudaFuncSetAttribute(phaseB, cudaFuncAttributeMaxDynamicSharedMemorySize,
                             (int)sizeof(SmemB));
        attr_done = true;
    }

    init_tables<<<1, 512>>>();
    phaseA<<<NBLKS, 512, sizeof(SmemA)>>>(x);
    midscanA<<<NSUP, 288>>>();
    midscanC<<<NSUP, 288>>>();
    phaseB<<<NBLKS, 512, sizeof(SmemB)>>>(out);
    fixup<<<NBLKS, 384>>>(out);
}